// round 12
// baseline (speedup 1.0000x reference)
#include <cuda_runtime.h>
#include <cuda_bf16.h>
#include <cstdint>

// Problem sizes (fixed by the reference)
#define MM 8192
#define KK 4096
#define NN 11008

#define BM 128
#define BN 128
#define BKB 128              // K bytes per pipeline stage
#define NKT (KK / BKB)       // 32
#define TILES_M (MM / BM)    // 64
#define TILES_N (NN / BN)    // 86
#define STAGES 3
#define TILE_BYTES (128 * BKB)           // 16 KB per matrix per stage
#define STAGE_BYTES (2 * TILE_BYTES)     // A + B
#define SMEM_DYN (STAGES * STAGE_BYTES + 1024)

// -------- scratch (device globals: allocation-free per harness rules) --------
__device__ __align__(16) int8_t g_q[(size_t)MM * KK];   // quantized activations
__device__ __align__(16) int8_t g_w[(size_t)NN * KK];   // unpacked weights {-1,0,1,2}
__device__ float g_s[MM];                               // per-row s = 127/max

// ---------------------------------------------------------------------------
// Kernel 1: per-row abs-max + int8 quantization.  One block per row.
// ---------------------------------------------------------------------------
__global__ __launch_bounds__(256) void rowquant_kernel(const float* __restrict__ x) {
    const int m = blockIdx.x;
    const int tid = threadIdx.x;
    const int lane = tid & 31;
    const int wid = tid >> 5;

    const float4* xr = reinterpret_cast<const float4*>(x + (size_t)m * KK);
    float4 v[4];
    float mx = 0.f;
#pragma unroll
    for (int i = 0; i < 4; i++) {
        v[i] = xr[tid + i * 256];
        mx = fmaxf(mx, fmaxf(fmaxf(fabsf(v[i].x), fabsf(v[i].y)),
                             fmaxf(fabsf(v[i].z), fabsf(v[i].w))));
    }
#pragma unroll
    for (int o = 16; o > 0; o >>= 1)
        mx = fmaxf(mx, __shfl_xor_sync(0xffffffffu, mx, o));

    __shared__ float red[8];
    if (lane == 0) red[wid] = mx;
    __syncthreads();
    float mall = red[0];
#pragma unroll
    for (int i = 1; i < 8; i++) mall = fmaxf(mall, red[i]);

    const float mclip = fmaxf(mall, 1e-5f);
    const float s = __fdiv_rn(127.0f, mclip);
    if (tid == 0) g_s[m] = s;

    int* qo = reinterpret_cast<int*>(g_q) + (size_t)m * (KK / 4);
#pragma unroll
    for (int i = 0; i < 4; i++) {
        int i0 = max(-128, min(127, __float2int_rn(__fmul_rn(v[i].x, s))));
        int i1 = max(-128, min(127, __float2int_rn(__fmul_rn(v[i].y, s))));
        int i2 = max(-128, min(127, __float2int_rn(__fmul_rn(v[i].z, s))));
        int i3 = max(-128, min(127, __float2int_rn(__fmul_rn(v[i].w, s))));
        qo[tid + i * 256] = (i0 & 0xff) | ((i1 & 0xff) << 8) |
                            ((i2 & 0xff) << 16) | ((i3 & 0xff) << 24);
    }
}

// ---------------------------------------------------------------------------
// Kernel 2: unpack 2-bit weights (code - 1 in {-1,0,1,2}) into int8.
// ---------------------------------------------------------------------------
__global__ __launch_bounds__(256) void unpack_kernel(const int* __restrict__ w) {
    const size_t total = (size_t)NN * (KK / 4);
    size_t i = (size_t)blockIdx.x * blockDim.x + threadIdx.x;
    if (i >= total) return;
    unsigned b = (unsigned)w[i] & 0xffu;
    unsigned spread = (b & 0x3u) | ((b & 0xCu) << 6) | ((b & 0x30u) << 12) | ((b & 0xC0u) << 18);
    reinterpret_cast<int*>(g_w)[i] = (int)__vsub4(spread, 0x01010101u);
}

// ---------------------------------------------------------------------------
// Kernel 3: int8 legacy tensor-core GEMM (mma.sync m16n8k32 s8s8s32).
// BK=128 bytes per stage, 3-stage cp.async, SW128 swizzle, ldmatrix.x4,
// ONE __syncthreads per k-iteration. f32 output, bf16-rounded values.
// ---------------------------------------------------------------------------
__device__ __forceinline__ void cpasync16(uint32_t s, const void* g) {
    asm volatile("cp.async.cg.shared.global [%0], [%1], 16;\n" :: "r"(s), "l"(g) : "memory");
}
__device__ __forceinline__ uint32_t sw128(uint32_t off) {
    return off ^ ((off >> 3) & 0x70u);   // XOR 16B-chunk index by row&7 (128B rows)
}
__device__ __forceinline__ void ldsm_x4(int& r0, int& r1, int& r2, int& r3, uint32_t addr) {
    asm volatile("ldmatrix.sync.aligned.m8n8.x4.shared.b16 {%0,%1,%2,%3}, [%4];\n"
                 : "=r"(r0), "=r"(r1), "=r"(r2), "=r"(r3) : "r"(addr));
}
__device__ __forceinline__ void mma_s8(int* c, const int* a, const int* b) {
    asm volatile(
        "mma.sync.aligned.m16n8k32.row.col.s32.s8.s8.s32 "
        "{%0,%1,%2,%3}, {%4,%5,%6,%7}, {%8,%9}, {%0,%1,%2,%3};\n"
        : "+r"(c[0]), "+r"(c[1]), "+r"(c[2]), "+r"(c[3])
        : "r"(a[0]), "r"(a[1]), "r"(a[2]), "r"(a[3]), "r"(b[0]), "r"(b[1]));
}
__device__ __forceinline__ float bf16_round(float v) {
    return __bfloat162float(__float2bfloat16_rn(v));
}

__global__ __launch_bounds__(256, 2) void gemm_kernel(const float* __restrict__ wscale,
                                                      float* __restrict__ out) {
    extern __shared__ int8_t smraw[];
    const uint32_t raw_u = (uint32_t)__cvta_generic_to_shared(smraw);
    const uint32_t base_u = (raw_u + 1023u) & ~1023u;

    // rasterize blocks in groups of 8 m-tiles so a wave's B panel fits in L2
    const int bid = blockIdx.y * gridDim.x + blockIdx.x;
    const int GROUP = 8;
    const int group_sz = GROUP * TILES_N;
    const int g = bid / group_sz;
    const int rem = bid - g * group_sz;
    const int gm = g * GROUP;
    const int gh = min(GROUP, TILES_M - gm);
    const int bm = (gm + rem % gh) * BM;
    const int bn = (rem / gh) * BN;

    const int tid = threadIdx.x;
    const int lane = tid & 31;
    const int warp = tid >> 5;
    const int warpM = warp >> 2;       // 0..1 -> 64 rows each
    const int warpN = warp & 3;        // 0..3 -> 32 cols each
    const int gid = lane >> 2;
    const int tig = lane & 3;

    // copy roles: thread t stages row r = t>>1, chunks (t&1)*4 .. +3 (16B each)
    const int r = tid >> 1;
    const int cbase = (tid & 1) * 4;
    const int8_t* gq = g_q + (size_t)(bm + r) * KK;
    const int8_t* gw = g_w + (size_t)(bn + r) * KK;
    uint32_t offs[4];
#pragma unroll
    for (int i = 0; i < 4; i++)
        offs[i] = sw128((uint32_t)(r * 128 + (cbase + i) * 16));

    uint32_t sA[STAGES], sB[STAGES];
#pragma unroll
    for (int s = 0; s < STAGES; s++) {
        sA[s] = base_u + s * STAGE_BYTES;
        sB[s] = sA[s] + TILE_BYTES;
    }

    // ldmatrix lane address components
    const int lrow8 = lane & 7;        // row within 8x16B matrix
    const int lmi = lane >> 3;         // matrix index 0..3

    int acc[4][4][4];
#pragma unroll
    for (int i = 0; i < 4; i++)
#pragma unroll
        for (int j = 0; j < 4; j++)
#pragma unroll
            for (int t = 0; t < 4; t++) acc[i][j][t] = 0;

    // prologue: issue stages 0..STAGES-2
#pragma unroll
    for (int s = 0; s < STAGES - 1; s++) {
        const int k0 = s * BKB;
#pragma unroll
        for (int i = 0; i < 4; i++) {
            cpasync16(sA[s] + offs[i], gq + k0 + (cbase + i) * 16);
            cpasync16(sB[s] + offs[i], gw + k0 + (cbase + i) * 16);
        }
        asm volatile("cp.async.commit_group;\n" ::: "memory");
    }

#pragma unroll 1
    for (int kt = 0; kt < NKT; kt++) {
        asm volatile("cp.async.wait_group %0;\n" :: "n"(STAGES - 2) : "memory");
        __syncthreads();   // stage kt ready; all warps done with stage kt-1

        // issue stage kt+STAGES-1 into the buffer consumed at kt-1 (safe)
        if (kt + STAGES - 1 < NKT) {
            const int ns = (kt + STAGES - 1) % STAGES;
            const int k0 = (kt + STAGES - 1) * BKB;
#pragma unroll
            for (int i = 0; i < 4; i++) {
                cpasync16(sA[ns] + offs[i], gq + k0 + (cbase + i) * 16);
                cpasync16(sB[ns] + offs[i], gw + k0 + (cbase + i) * 16);
            }
            asm volatile("cp.async.commit_group;\n" ::: "memory");
        }

        const int st = kt % STAGES;
        const uint32_t cA = sA[st];
        const uint32_t cB = sB[st];

#pragma unroll
        for (int kk = 0; kk < BKB; kk += 32) {
            int a[4][4];
#pragma unroll
            for (int i = 0; i < 4; i++) {
                // x4 matrices: (rows 0-7 / 8-15) x (k-half 0 / 1)
                int row = warpM * 64 + i * 16 + (lmi & 1) * 8 + lrow8;
                int cb = kk + (lmi >> 1) * 16;
                ldsm_x4(a[i][0], a[i][1], a[i][2], a[i][3],
                        cA + sw128((uint32_t)(row * 128 + cb)));
            }
            int b[4][2];
            {
                int nr = warpN * 32 + lmi * 8 + lrow8;
                int r0, r1, r2, r3;
                ldsm_x4(r0, r1, r2, r3, cB + sw128((uint32_t)(nr * 128 + kk)));
                b[0][0] = r0; b[1][0] = r1; b[2][0] = r2; b[3][0] = r3;
                ldsm_x4(r0, r1, r2, r3, cB + sw128((uint32_t)(nr * 128 + kk + 16)));
                b[0][1] = r0; b[1][1] = r1; b[2][1] = r2; b[3][1] = r3;
            }
#pragma unroll
            for (int i = 0; i < 4; i++)
#pragma unroll
                for (int j = 0; j < 4; j++) mma_s8(acc[i][j], a[i], b[j]);
        }
    }

    // epilogue — (acc / s) * ws in IEEE RN f32, rounded through bf16, f32 out
    const float wsa = wscale[(tig * 2) & 3];
    const float wsb = wscale[(tig * 2 + 1) & 3];
#pragma unroll
    for (int i = 0; i < 4; i++) {
        const int m0 = bm + warpM * 64 + i * 16 + gid;
        const float s0 = g_s[m0];
        const float s1 = g_s[m0 + 8];
#pragma unroll
        for (int j = 0; j < 4; j++) {
            const int n0 = bn + warpN * 32 + j * 8 + tig * 2;
            const size_t o0 = (size_t)m0 * NN + n0;
            float2 p0, p1;
            p0.x = bf16_round(__fmul_rn(__fdiv_rn((float)acc[i][j][0], s0), wsa));
            p0.y = bf16_round(__fmul_rn(__fdiv_rn((float)acc[i][j][1], s0), wsb));
            p1.x = bf16_round(__fmul_rn(__fdiv_rn((float)acc[i][j][2], s1), wsa));
            p1.y = bf16_round(__fmul_rn(__fdiv_rn((float)acc[i][j][3], s1), wsb));
            *reinterpret_cast<float2*>(out + o0) = p0;
            *reinterpret_cast<float2*>(out + o0 + (size_t)8 * NN) = p1;
        }
    }
}

// ---------------------------------------------------------------------------
extern "C" void kernel_launch(void* const* d_in, const int* in_sizes, int n_in,
                              void* d_out, int out_size) {
    // Identify inputs by element count (robust to metadata ordering)
    const float* x = nullptr;
    const int* w = nullptr;
    const float* wscale = nullptr;
    for (int i = 0; i < n_in; i++) {
        if (in_sizes[i] == MM * KK)            x = (const float*)d_in[i];
        else if (in_sizes[i] == NN * (KK / 4)) w = (const int*)d_in[i];
        else if (in_sizes[i] == 4)             wscale = (const float*)d_in[i];
    }
    float* out = (float*)d_out;   // output dtype: float32 (bf16-rounded values)

    rowquant_kernel<<<MM, 256>>>(x);

    const size_t upk = (size_t)NN * (KK / 4);
    unpack_kernel<<<(unsigned)((upk + 255) / 256), 256>>>(w);

    cudaFuncSetAttribute(gemm_kernel, cudaFuncAttributeMaxDynamicSharedMemorySize, SMEM_DYN);
    dim3 grid(TILES_N, TILES_M);
    gemm_kernel<<<grid, 256, SMEM_DYN>>>(wscale, out);
}

// round 14
// speedup vs baseline: 3.0176x; 3.0176x over previous
#include <cuda_runtime.h>
#include <cuda_bf16.h>
#include <cstdint>

// Problem sizes (fixed by the reference)
#define MM 8192
#define KK 4096
#define NN 11008

#define BM 128
#define BN 128
#define BKE 64               // K elements per pipeline stage (128 bytes bf16)
#define NKT (KK / BKE)       // 64
#define TILES_M (MM / BM)    // 64
#define TILES_N (NN / BN)    // 86
#define STAGES 3
#define TILE_BYTES (128 * 128)           // 16 KB per matrix per stage
#define STAGE_BYTES (2 * TILE_BYTES)     // A + B
#define SMEM_DYN (STAGES * STAGE_BYTES + 1024)

// -------- scratch (device globals: allocation-free per harness rules) --------
__device__ __align__(16) __nv_bfloat16 g_q[(size_t)MM * KK];   // quantized activations (bf16 ints)
__device__ __align__(16) __nv_bfloat16 g_w[(size_t)NN * KK];   // unpacked weights {-1,0,1,2} (bf16)
__device__ float g_s[MM];                                      // per-row s = 127/max

// ---------------------------------------------------------------------------
// Kernel 1: per-row abs-max + int8-range quantization -> bf16.  One block/row.
// ---------------------------------------------------------------------------
__global__ __launch_bounds__(256) void rowquant_kernel(const float* __restrict__ x) {
    const int m = blockIdx.x;
    const int tid = threadIdx.x;
    const int lane = tid & 31;
    const int wid = tid >> 5;

    const float4* xr = reinterpret_cast<const float4*>(x + (size_t)m * KK);
    float4 v[4];
    float mx = 0.f;
#pragma unroll
    for (int i = 0; i < 4; i++) {
        v[i] = xr[tid + i * 256];
        mx = fmaxf(mx, fmaxf(fmaxf(fabsf(v[i].x), fabsf(v[i].y)),
                             fmaxf(fabsf(v[i].z), fabsf(v[i].w))));
    }
#pragma unroll
    for (int o = 16; o > 0; o >>= 1)
        mx = fmaxf(mx, __shfl_xor_sync(0xffffffffu, mx, o));

    __shared__ float red[8];
    if (lane == 0) red[wid] = mx;
    __syncthreads();
    float mall = red[0];
#pragma unroll
    for (int i = 1; i < 8; i++) mall = fmaxf(mall, red[i]);

    const float mclip = fmaxf(mall, 1e-5f);
    const float s = __fdiv_rn(127.0f, mclip);
    if (tid == 0) g_s[m] = s;

    uint2* qo = reinterpret_cast<uint2*>(g_q + (size_t)m * KK);
#pragma unroll
    for (int i = 0; i < 4; i++) {
        int i0 = max(-128, min(127, __float2int_rn(__fmul_rn(v[i].x, s))));
        int i1 = max(-128, min(127, __float2int_rn(__fmul_rn(v[i].y, s))));
        int i2 = max(-128, min(127, __float2int_rn(__fmul_rn(v[i].z, s))));
        int i3 = max(-128, min(127, __float2int_rn(__fmul_rn(v[i].w, s))));
        unsigned h0 = __bfloat16_as_ushort(__float2bfloat16_rn((float)i0));
        unsigned h1 = __bfloat16_as_ushort(__float2bfloat16_rn((float)i1));
        unsigned h2 = __bfloat16_as_ushort(__float2bfloat16_rn((float)i2));
        unsigned h3 = __bfloat16_as_ushort(__float2bfloat16_rn((float)i3));
        uint2 p;
        p.x = h0 | (h1 << 16);
        p.y = h2 | (h3 << 16);
        qo[tid + i * 256] = p;   // 4 consecutive bf16 at element (tid+i*256)*4
    }
}

// ---------------------------------------------------------------------------
// Kernel 2: unpack 2-bit weights (code - 1 in {-1,0,1,2}) into bf16.
// column j = 4*p + i <- bits (2i, 2i+1) of packed byte p.
// ---------------------------------------------------------------------------
__global__ __launch_bounds__(256) void unpack_kernel(const int* __restrict__ w) {
    const size_t total = (size_t)NN * (KK / 4);
    size_t i = (size_t)blockIdx.x * blockDim.x + threadIdx.x;
    if (i >= total) return;
    const unsigned b = (unsigned)w[i] & 0xffu;
    // bf16 bit patterns for code-1: -1, 0, 1, 2
    const unsigned T[4] = {0xBF80u, 0x0000u, 0x3F80u, 0x4000u};
    unsigned c0 = T[b & 3u];
    unsigned c1 = T[(b >> 2) & 3u];
    unsigned c2 = T[(b >> 4) & 3u];
    unsigned c3 = T[(b >> 6) & 3u];
    uint2 p;
    p.x = c0 | (c1 << 16);
    p.y = c2 | (c3 << 16);
    reinterpret_cast<uint2*>(g_w)[i] = p;
}

// ---------------------------------------------------------------------------
// Kernel 3: bf16 tensor-core GEMM (mma.sync m16n8k16 f32.bf16.bf16.f32).
// Exact integer arithmetic (|acc| < 2^24). 3-stage cp.async, SW128 swizzle,
// ldmatrix.x4, round-8 control flow. f32 output, bf16-rounded values.
// ---------------------------------------------------------------------------
__device__ __forceinline__ void cpasync16(uint32_t s, const void* g) {
    asm volatile("cp.async.cg.shared.global [%0], [%1], 16;\n" :: "r"(s), "l"(g) : "memory");
}
__device__ __forceinline__ uint32_t sw128(uint32_t off) {
    return off ^ ((off >> 3) & 0x70u);   // canonical SW128 on 128B rows
}
__device__ __forceinline__ void ldsm_x4(int& r0, int& r1, int& r2, int& r3, uint32_t addr) {
    asm volatile("ldmatrix.sync.aligned.m8n8.x4.shared.b16 {%0,%1,%2,%3}, [%4];\n"
                 : "=r"(r0), "=r"(r1), "=r"(r2), "=r"(r3) : "r"(addr));
}
__device__ __forceinline__ void mma_bf16(float* c, const int* a, const int* b) {
    asm volatile(
        "mma.sync.aligned.m16n8k16.row.col.f32.bf16.bf16.f32 "
        "{%0,%1,%2,%3}, {%4,%5,%6,%7}, {%8,%9}, {%0,%1,%2,%3};\n"
        : "+f"(c[0]), "+f"(c[1]), "+f"(c[2]), "+f"(c[3])
        : "r"(a[0]), "r"(a[1]), "r"(a[2]), "r"(a[3]), "r"(b[0]), "r"(b[1]));
}
__device__ __forceinline__ float bf16_round(float v) {
    return __bfloat162float(__float2bfloat16_rn(v));
}

__global__ __launch_bounds__(256, 2) void gemm_kernel(const float* __restrict__ wscale,
                                                      float* __restrict__ out) {
    extern __shared__ int8_t smraw[];
    const uint32_t raw_u = (uint32_t)__cvta_generic_to_shared(smraw);
    const uint32_t base_u = (raw_u + 1023u) & ~1023u;

    // rasterize blocks in groups of 8 m-tiles so a wave's B panel fits in L2
    const int bid = blockIdx.y * gridDim.x + blockIdx.x;
    const int GROUP = 8;
    const int group_sz = GROUP * TILES_N;
    const int g = bid / group_sz;
    const int rem = bid - g * group_sz;
    const int gm = g * GROUP;
    const int gh = min(GROUP, TILES_M - gm);
    const int bm = (gm + rem % gh) * BM;
    const int bn = (rem / gh) * BN;

    const int tid = threadIdx.x;
    const int lane = tid & 31;
    const int warp = tid >> 5;
    const int warpM = warp >> 2;       // 0..1 -> 64 rows each
    const int warpN = warp & 3;        // 0..3 -> 32 cols each
    const int gid = lane >> 2;
    const int tig = lane & 3;

    // copy roles: thread t stages row r = t>>1, chunks (t&1)*4 .. +3 (16B each)
    const int r = tid >> 1;
    const int cbase = (tid & 1) * 4;
    const char* gq = (const char*)(g_q + (size_t)(bm + r) * KK);
    const char* gw = (const char*)(g_w + (size_t)(bn + r) * KK);
    uint32_t offs[4];
#pragma unroll
    for (int i = 0; i < 4; i++)
        offs[i] = sw128((uint32_t)(r * 128 + (cbase + i) * 16));

    uint32_t sA[STAGES], sB[STAGES];
#pragma unroll
    for (int s = 0; s < STAGES; s++) {
        sA[s] = base_u + s * STAGE_BYTES;
        sB[s] = sA[s] + TILE_BYTES;
    }

    // ldmatrix lane address components
    const int lrow8 = lane & 7;        // row within 8x16B matrix
    const int lmi = lane >> 3;         // matrix index 0..3

    float acc[4][4][4];
#pragma unroll
    for (int i = 0; i < 4; i++)
#pragma unroll
        for (int j = 0; j < 4; j++)
#pragma unroll
            for (int t = 0; t < 4; t++) acc[i][j][t] = 0.f;

    // prologue: issue stages 0..STAGES-2 (stage = 128 bytes of K per row)
#pragma unroll
    for (int s = 0; s < STAGES - 1; s++) {
        const int k0 = s * 128;        // byte offset along K
#pragma unroll
        for (int i = 0; i < 4; i++) {
            cpasync16(sA[s] + offs[i], gq + k0 + (cbase + i) * 16);
            cpasync16(sB[s] + offs[i], gw + k0 + (cbase + i) * 16);
        }
        asm volatile("cp.async.commit_group;\n" ::: "memory");
    }

#pragma unroll 1
    for (int kt = 0; kt < NKT; kt++) {
        asm volatile("cp.async.wait_group %0;\n" :: "n"(STAGES - 2) : "memory");
        __syncthreads();

        const int st = kt % STAGES;
        const uint32_t cA = sA[st];
        const uint32_t cB = sB[st];

#pragma unroll
        for (int ks = 0; ks < 4; ks++) {     // 4 k16 steps per stage
            const int cb = ks * 32;          // byte base of this k16 step
            int a[4][4];
#pragma unroll
            for (int i = 0; i < 4; i++) {
                // x4 matrices: (rows 0-7 / 8-15) x (k-half 0 / 1)
                int row = warpM * 64 + i * 16 + (lmi & 1) * 8 + lrow8;
                int cc = cb + (lmi >> 1) * 16;
                ldsm_x4(a[i][0], a[i][1], a[i][2], a[i][3],
                        cA + sw128((uint32_t)(row * 128 + cc)));
            }
            int b[4][2];
            {
                int nr = warpN * 32 + lmi * 8 + lrow8;
                int r0, r1, r2, r3;
                ldsm_x4(r0, r1, r2, r3, cB + sw128((uint32_t)(nr * 128 + cb)));
                b[0][0] = r0; b[1][0] = r1; b[2][0] = r2; b[3][0] = r3;
                ldsm_x4(r0, r1, r2, r3, cB + sw128((uint32_t)(nr * 128 + cb + 16)));
                b[0][1] = r0; b[1][1] = r1; b[2][1] = r2; b[3][1] = r3;
            }
#pragma unroll
            for (int i = 0; i < 4; i++)
#pragma unroll
                for (int j = 0; j < 4; j++) mma_bf16(acc[i][j], a[i], b[j]);
        }
        __syncthreads();

        // issue stage kt+STAGES-1 (overwrites buffer consumed at kt-1)
        if (kt + STAGES - 1 < NKT) {
            const int k0 = (kt + STAGES - 1) * 128;
            const int ns = (kt + STAGES - 1) % STAGES;
#pragma unroll
            for (int i = 0; i < 4; i++) {
                cpasync16(sA[ns] + offs[i], gq + k0 + (cbase + i) * 16);
                cpasync16(sB[ns] + offs[i], gw + k0 + (cbase + i) * 16);
            }
        }
        asm volatile("cp.async.commit_group;\n" ::: "memory");
    }

    // epilogue — (acc / s) * ws in IEEE RN f32, rounded through bf16, f32 out
    const float wsa = wscale[(tig * 2) & 3];
    const float wsb = wscale[(tig * 2 + 1) & 3];
#pragma unroll
    for (int i = 0; i < 4; i++) {
        const int m0 = bm + warpM * 64 + i * 16 + gid;
        const float s0 = g_s[m0];
        const float s1 = g_s[m0 + 8];
#pragma unroll
        for (int j = 0; j < 4; j++) {
            const int n0 = bn + warpN * 32 + j * 8 + tig * 2;
            const size_t o0 = (size_t)m0 * NN + n0;
            float2 p0, p1;
            p0.x = bf16_round(__fmul_rn(__fdiv_rn(acc[i][j][0], s0), wsa));
            p0.y = bf16_round(__fmul_rn(__fdiv_rn(acc[i][j][1], s0), wsb));
            p1.x = bf16_round(__fmul_rn(__fdiv_rn(acc[i][j][2], s1), wsa));
            p1.y = bf16_round(__fmul_rn(__fdiv_rn(acc[i][j][3], s1), wsb));
            *reinterpret_cast<float2*>(out + o0) = p0;
            *reinterpret_cast<float2*>(out + o0 + (size_t)8 * NN) = p1;
        }
    }
}

// ---------------------------------------------------------------------------
extern "C" void kernel_launch(void* const* d_in, const int* in_sizes, int n_in,
                              void* d_out, int out_size) {
    // Identify inputs by element count (robust to metadata ordering)
    const float* x = nullptr;
    const int* w = nullptr;
    const float* wscale = nullptr;
    for (int i = 0; i < n_in; i++) {
        if (in_sizes[i] == MM * KK)            x = (const float*)d_in[i];
        else if (in_sizes[i] == NN * (KK / 4)) w = (const int*)d_in[i];
        else if (in_sizes[i] == 4)             wscale = (const float*)d_in[i];
    }
    float* out = (float*)d_out;   // output dtype: float32 (bf16-rounded values)

    rowquant_kernel<<<MM, 256>>>(x);

    const size_t upk = (size_t)NN * (KK / 4);
    unpack_kernel<<<(unsigned)((upk + 255) / 256), 256>>>(w);

    cudaFuncSetAttribute(gemm_kernel, cudaFuncAttributeMaxDynamicSharedMemorySize, SMEM_DYN);
    dim3 grid(TILES_N, TILES_M);
    gemm_kernel<<<grid, 256, SMEM_DYN>>>(wscale, out);
}